// round 16
// baseline (speedup 1.0000x reference)
#include <cuda_runtime.h>
#include <cuda_fp16.h>
#include <cstdint>

#define T_LEN 2048
#define BATCH 8
#define EMBED 1024
#define NHEADS 16
#define HDIM 64
#define BH 128            // BATCH * NHEADS
#define MROWS 16384       // T_LEN * BATCH
#define NQKV 3072         // 3 * EMBED

// ---- GEMM geometry: 256x128 block, 8 warps (4x2), warp tile 64x64 ----
#define BM 256
#define BN 128
#define BKH 64            // k halves per stage (128B rows)
#define GTLD 72           // smem leading dim (halves)
#define GSTAGES 4
#define A_TILEH (BM * GTLD)
#define B_TILEH (BN * GTLD)
#define STAGE_H (A_TILEH + B_TILEH)
#define GEMM_SMEM (GSTAGES * STAGE_H * 2)    // 221184 B, 1 CTA/SM

// attention smem layout (bytes) -- 94 KB -> 2 CTAs/SM
#define QH_LD 72
#define VT_LD 136
#define PH_LD 136
#define OFF_QH   0
#define OFF_KH   (OFF_QH + BH * QH_LD * 2)
#define OFF_VT   (OFF_KH + BH * QH_LD * 2)
#define OFF_PH   (OFF_VT + HDIM * VT_LD * 2)
#define OFF_IQ   (OFF_PH + BH * PH_LD * 2)
#define OFF_IK   (OFF_IQ + BH * 4)
#define OFF_RMAX (OFF_IK + BH * 4)
#define OFF_RSUM (OFF_RMAX + 4 * BH * 4)
#define ATTN_SMEM (OFF_RSUM + 4 * BH * 4)    // 94208

// Scratch (allowed: __device__ globals, no dynamic allocation)
__device__ __half g_qkv[(size_t)MROWS * NQKV];    // [T*B, 3E] fp16
__device__ __half g_ws[(size_t)MROWS * EMBED];    // [B, T, E] fp16
__device__ __half g_qh[(size_t)MROWS * EMBED];    // query fp16
__device__ __half g_wqkv[(size_t)NQKV * EMBED];   // w_qkv fp16
__device__ __half g_wout[(size_t)EMBED * EMBED];  // w_out fp16

#define LDM_X4(r0, r1, r2, r3, p) \
    asm volatile("ldmatrix.sync.aligned.m8n8.x4.b16 {%0,%1,%2,%3}, [%4];\n" \
                 : "=r"(r0), "=r"(r1), "=r"(r2), "=r"(r3) \
                 : "r"((uint32_t)__cvta_generic_to_shared(p)))

#define MMA_F16(c, af, b0, b1) \
    asm volatile("mma.sync.aligned.m16n8k16.row.col.f32.f16.f16.f32 " \
                 "{%0,%1,%2,%3}, {%4,%5,%6,%7}, {%8,%9}, {%0,%1,%2,%3};\n" \
                 : "+f"((c)[0]), "+f"((c)[1]), "+f"((c)[2]), "+f"((c)[3]) \
                 : "r"((af)[0]), "r"((af)[1]), "r"((af)[2]), "r"((af)[3]), \
                   "r"(b0), "r"(b1))

// ---------------------------------------------------------------------------
// Elementwise fp32 -> fp16 conversion, float4-vectorized.
// ---------------------------------------------------------------------------
__global__ __launch_bounds__(256) void to_half_kernel(
    const float* __restrict__ x, __half* __restrict__ y, int n4)
{
    int i = blockIdx.x * blockDim.x + threadIdx.x;
    if (i < n4) {
        float4 v = ((const float4*)x)[i];
        __half2* y2 = (__half2*)y;
        y2[2 * i]     = __floats2half2_rn(v.x, v.y);
        y2[2 * i + 1] = __floats2half2_rn(v.z, v.w);
    }
}

// ---------------------------------------------------------------------------
// fp16 tensor-core GEMM (fp32 accumulate): C[m][n] = sum_k A[m][k]*B[n][k]+bias[n]
// 256x128 block tile, 8 warps (4 m x 2 n), warp tile 64x64.
// Per ks: 8 ldmatrix.x4 feed 32 mma (LSU cyc/mma = 1.0 vs 1.5 before).
// 4-stage cp.async pipeline (221 KB smem, 1 CTA/SM).
// OutT = __half (QKV intermediate) or float (final output).
// M mult of 256, N mult of 128, K mult of 64.
// ---------------------------------------------------------------------------
template <typename OutT>
__global__ __launch_bounds__(256) void gemm_f16_big(
    const __half* __restrict__ A, const __half* __restrict__ B,
    const float* __restrict__ bias, OutT* __restrict__ C,
    int N, int K)
{
    extern __shared__ __half smh[];
    const int tid  = threadIdx.x;
    const int lane = tid & 31;
    const int warp = tid >> 5;
    const int wm   = warp >> 1;        // 0..3
    const int wn   = warp & 1;         // 0..1
    const int bm   = blockIdx.y * BM;
    const int bn   = blockIdx.x * BN;

    const int lrow   = tid >> 3;       // 0..31
    const int lchunk = tid & 7;        // 0..7
    const __half* gA = A + (size_t)(bm + lrow) * K + lchunk * 8;
    const __half* gB = B + (size_t)(bn + lrow) * K + lchunk * 8;

    const int a_row  = wm * 64 + (lane & 15);                     // + mf*16
    const int a_koff = (lane >> 4) * 8;
    const int b_row  = wn * 64 + ((lane >> 4) & 1) * 8 + (lane & 7); // + bi*16
    const int b_koff = ((lane >> 3) & 1) * 8;

    float c[4][8][4];
#pragma unroll
    for (int mf = 0; mf < 4; mf++)
#pragma unroll
        for (int nf = 0; nf < 8; nf++)
#pragma unroll
            for (int r = 0; r < 4; r++) c[mf][nf][r] = 0.0f;

    const int ntiles = K >> 6;

#define LOAD_TILE(s, k0) do {                                                  \
    __half* As_ = smh + (s) * STAGE_H;                                         \
    __half* Bs_ = As_ + A_TILEH;                                               \
    _Pragma("unroll")                                                          \
    for (int i_ = 0; i_ < 8; i_++) {                                           \
        uint32_t sa_ = (uint32_t)__cvta_generic_to_shared(                     \
            As_ + (lrow + i_ * 32) * GTLD + lchunk * 8);                       \
        asm volatile("cp.async.cg.shared.global [%0], [%1], 16;\n"             \
                     :: "r"(sa_), "l"(gA + (size_t)(i_ * 32) * K + (k0)));     \
    }                                                                          \
    _Pragma("unroll")                                                          \
    for (int i_ = 0; i_ < 4; i_++) {                                           \
        uint32_t sb_ = (uint32_t)__cvta_generic_to_shared(                     \
            Bs_ + (lrow + i_ * 32) * GTLD + lchunk * 8);                       \
        asm volatile("cp.async.cg.shared.global [%0], [%1], 16;\n"             \
                     :: "r"(sb_), "l"(gB + (size_t)(i_ * 32) * K + (k0)));     \
    }                                                                          \
} while (0)

    // prologue: tiles 0 .. GSTAGES-2
#pragma unroll
    for (int s = 0; s < GSTAGES - 1; s++) {
        LOAD_TILE(s, s * BKH);
        asm volatile("cp.async.commit_group;\n");
    }

    for (int kt = 0; kt < ntiles; kt++) {
        asm volatile("cp.async.wait_group %0;\n" :: "n"(GSTAGES - 2));
        __syncthreads();

        int pf = kt + GSTAGES - 1;
        if (pf < ntiles) LOAD_TILE(pf % GSTAGES, pf * BKH);
        asm volatile("cp.async.commit_group;\n");

        const __half* As = smh + (kt % GSTAGES) * STAGE_H;
        const __half* Bs = As + A_TILEH;

#pragma unroll
        for (int ks = 0; ks < 4; ks++) {            // 4 x k16 per BKH=64
            uint32_t afr[4][4];
#pragma unroll
            for (int mf = 0; mf < 4; mf++)
                LDM_X4(afr[mf][0], afr[mf][1], afr[mf][2], afr[mf][3],
                       As + (a_row + mf * 16) * GTLD + ks * 16 + a_koff);
            uint32_t bfr[8][2];
#pragma unroll
            for (int bi = 0; bi < 4; bi++)
                LDM_X4(bfr[2 * bi][0], bfr[2 * bi][1],
                       bfr[2 * bi + 1][0], bfr[2 * bi + 1][1],
                       Bs + (b_row + bi * 16) * GTLD + ks * 16 + b_koff);
#pragma unroll
            for (int mf = 0; mf < 4; mf++)
#pragma unroll
                for (int nf = 0; nf < 8; nf++)
                    MMA_F16(c[mf][nf], afr[mf], bfr[nf][0], bfr[nf][1]);
        }
    }

    // epilogue
#pragma unroll
    for (int mf = 0; mf < 4; mf++) {
        int r0 = bm + wm * 64 + mf * 16 + (lane >> 2);
#pragma unroll
        for (int nf = 0; nf < 8; nf++) {
            int col = bn + wn * 64 + nf * 8 + ((lane & 3) << 1);
            float2 bv = *(const float2*)(bias + col);
            float v00 = c[mf][nf][0] + bv.x, v01 = c[mf][nf][1] + bv.y;
            float v10 = c[mf][nf][2] + bv.x, v11 = c[mf][nf][3] + bv.y;
            if (sizeof(OutT) == 2) {
                __half2* p0 = (__half2*)((__half*)C + (size_t)r0 * N + col);
                __half2* p1 = (__half2*)((__half*)C + (size_t)(r0 + 8) * N + col);
                *p0 = __floats2half2_rn(v00, v01);
                *p1 = __floats2half2_rn(v10, v11);
            } else {
                *(float2*)((float*)C + (size_t)r0 * N + col)
                    = make_float2(v00, v01);
                *(float2*)((float*)C + (size_t)(r0 + 8) * N + col)
                    = make_float2(v10, v11);
            }
        }
    }
#undef LOAD_TILE
}

// ---------------------------------------------------------------------------
// Per-t tensor-core attention, register-resident softmax. g_qkv is fp16:
// straight uint4 copies into tiles (no conversion). Logic unchanged from R14.
// ---------------------------------------------------------------------------
__global__ __launch_bounds__(256, 2) void attn_kernel()
{
    extern __shared__ char smem[];
    __half* qh   = (__half*)(smem + OFF_QH);   // 128 x 72
    __half* kh   = (__half*)(smem + OFF_KH);   // 128 x 72
    __half* vt   = (__half*)(smem + OFF_VT);   // 64 x 136 (transposed: [d][j])
    __half* ph   = (__half*)(smem + OFF_PH);   // 128 x 136 (exp values)
    float*  invq = (float*)(smem + OFF_IQ);    // 128
    float*  invk = (float*)(smem + OFF_IK);    // 128
    float*  rmax = (float*)(smem + OFF_RMAX);  // [4][128]
    float*  rsum = (float*)(smem + OFF_RSUM);  // [4][128]

    const int t = blockIdx.x;
    const int tid = threadIdx.x;
    const int lane = tid & 31;
    const int warp = tid >> 5;
    const int wm = warp >> 2;      // 0..1
    const int wn = warp & 3;       // 0..3

    // Load q,k,v (fp16, 16B chunks); v stored transposed vt[d][j]
    for (int idx = tid; idx < BH * (HDIM / 8); idx += 256) {
        int a  = idx >> 3;                 // row 0..127
        int d8 = (idx & 7) << 3;           // 0,8,..,56
        int b = a >> 4, h = a & 15;
        const __half* base = g_qkv + (size_t)(t * BATCH + b) * NQKV
                             + h * HDIM + d8;
        uint4 qv = *(const uint4*)(base);
        uint4 kv = *(const uint4*)(base + EMBED);
        uint4 vv = *(const uint4*)(base + 2 * EMBED);
        *(uint4*)(qh + a * QH_LD + d8) = qv;
        *(uint4*)(kh + a * QH_LD + d8) = kv;
        const __half* vh = (const __half*)&vv;
#pragma unroll
        for (int j = 0; j < 8; j++)
            vt[(d8 + j) * VT_LD + a] = vh[j];
    }
    __syncthreads();

    // Row norms over fp16 values
    {
        const __half2* r = (const __half2*)((tid < BH ? qh : kh)
                            + (tid & 127) * QH_LD);
        float s = 0.0f;
#pragma unroll
        for (int d = 0; d < HDIM / 2; d++) {
            float2 f = __half22float2(r[d]);
            s = fmaf(f.x, f.x, fmaf(f.y, f.y, s));
        }
        float inv = rsqrtf(s);
        if (tid < BH) invq[tid] = inv; else invk[tid - BH] = inv;
    }
    __syncthreads();

    const int a_row  = wm * 64 + (lane & 15);
    const int a_koff = (lane >> 4) * 8;

    // S = qh @ kh^T (fp32 accum)
    float c[4][4][4];
    {
        const int b_row  = wn * 32 + ((lane >> 4) & 1) * 8 + (lane & 7);
        const int b_koff = ((lane >> 3) & 1) * 8;
#pragma unroll
        for (int mf = 0; mf < 4; mf++)
#pragma unroll
            for (int nf = 0; nf < 4; nf++)
#pragma unroll
                for (int r = 0; r < 4; r++) c[mf][nf][r] = 0.0f;

#pragma unroll
        for (int ks = 0; ks < 4; ks++) {
            uint32_t afr[4][4];
#pragma unroll
            for (int mf = 0; mf < 4; mf++)
                LDM_X4(afr[mf][0], afr[mf][1], afr[mf][2], afr[mf][3],
                       qh + (a_row + mf * 16) * QH_LD + ks * 16 + a_koff);
            uint32_t bfr[4][2];
#pragma unroll
            for (int bi = 0; bi < 2; bi++)
                LDM_X4(bfr[2 * bi][0], bfr[2 * bi][1],
                       bfr[2 * bi + 1][0], bfr[2 * bi + 1][1],
                       kh + (b_row + bi * 16) * QH_LD + ks * 16 + b_koff);
#pragma unroll
            for (int mf = 0; mf < 4; mf++)
#pragma unroll
                for (int nf = 0; nf < 4; nf++)
                    MMA_F16(c[mf][nf], afr[mf], bfr[nf][0], bfr[nf][1]);
        }
    }

    // Scale, per-warp row maxima via shfl, publish
#pragma unroll
    for (int mf = 0; mf < 4; mf++) {
        int r0 = wm * 64 + mf * 16 + (lane >> 2);
        float s0 = invq[r0] * 0.125f;
        float s1 = invq[r0 + 8] * 0.125f;
        float m0 = -1e30f, m1 = -1e30f;
#pragma unroll
        for (int nf = 0; nf < 4; nf++) {
            int col = wn * 32 + nf * 8 + ((lane & 3) << 1);
            float k0 = invk[col], k1 = invk[col + 1];
            c[mf][nf][0] *= s0 * k0; c[mf][nf][1] *= s0 * k1;
            c[mf][nf][2] *= s1 * k0; c[mf][nf][3] *= s1 * k1;
            m0 = fmaxf(m0, fmaxf(c[mf][nf][0], c[mf][nf][1]));
            m1 = fmaxf(m1, fmaxf(c[mf][nf][2], c[mf][nf][3]));
        }
        m0 = fmaxf(m0, __shfl_xor_sync(0xffffffffu, m0, 1));
        m0 = fmaxf(m0, __shfl_xor_sync(0xffffffffu, m0, 2));
        m1 = fmaxf(m1, __shfl_xor_sync(0xffffffffu, m1, 1));
        m1 = fmaxf(m1, __shfl_xor_sync(0xffffffffu, m1, 2));
        if ((lane & 3) == 0) {
            rmax[wn * BH + r0]     = m0;
            rmax[wn * BH + r0 + 8] = m1;
        }
    }
    __syncthreads();

    // exp(s - rowmax) -> ph (fp16, unnormalized), publish row sums
#pragma unroll
    for (int mf = 0; mf < 4; mf++) {
        int r0 = wm * 64 + mf * 16 + (lane >> 2);
        float M0 = fmaxf(fmaxf(rmax[r0], rmax[BH + r0]),
                         fmaxf(rmax[2 * BH + r0], rmax[3 * BH + r0]));
        float M1 = fmaxf(fmaxf(rmax[r0 + 8], rmax[BH + r0 + 8]),
                         fmaxf(rmax[2 * BH + r0 + 8], rmax[3 * BH + r0 + 8]));
        float sum0 = 0.0f, sum1 = 0.0f;
#pragma unroll
        for (int nf = 0; nf < 4; nf++) {
            int col = wn * 32 + nf * 8 + ((lane & 3) << 1);
            float e0 = __expf(c[mf][nf][0] - M0);
            float e1 = __expf(c[mf][nf][1] - M0);
            float e2 = __expf(c[mf][nf][2] - M1);
            float e3 = __expf(c[mf][nf][3] - M1);
            sum0 += e0 + e1; sum1 += e2 + e3;
            *(__half2*)(ph + r0 * PH_LD + col)       = __floats2half2_rn(e0, e1);
            *(__half2*)(ph + (r0 + 8) * PH_LD + col) = __floats2half2_rn(e2, e3);
        }
        sum0 += __shfl_xor_sync(0xffffffffu, sum0, 1);
        sum0 += __shfl_xor_sync(0xffffffffu, sum0, 2);
        sum1 += __shfl_xor_sync(0xffffffffu, sum1, 1);
        sum1 += __shfl_xor_sync(0xffffffffu, sum1, 2);
        if ((lane & 3) == 0) {
            rsum[wn * BH + r0]     = sum0;
            rsum[wn * BH + r0 + 8] = sum1;
        }
    }
    __syncthreads();

    float rinv0[4], rinv1[4];
#pragma unroll
    for (int mf = 0; mf < 4; mf++) {
        int r0 = wm * 64 + mf * 16 + (lane >> 2);
        rinv0[mf] = 1.0f / (rsum[r0] + rsum[BH + r0]
                            + rsum[2 * BH + r0] + rsum[3 * BH + r0]);
        rinv1[mf] = 1.0f / (rsum[r0 + 8] + rsum[BH + r0 + 8]
                            + rsum[2 * BH + r0 + 8] + rsum[3 * BH + r0 + 8]);
    }

    // ws = (1/sum) * E @ V
    {
        const int b_row  = wn * 16 + ((lane >> 4) & 1) * 8 + (lane & 7);
        const int b_koff = ((lane >> 3) & 1) * 8;

        float o[4][2][4];
#pragma unroll
        for (int mf = 0; mf < 4; mf++)
#pragma unroll
            for (int nf = 0; nf < 2; nf++)
#pragma unroll
                for (int r = 0; r < 4; r++) o[mf][nf][r] = 0.0f;

#pragma unroll
        for (int ks = 0; ks < 8; ks++) {
            uint32_t afr[4][4];
#pragma unroll
            for (int mf = 0; mf < 4; mf++)
                LDM_X4(afr[mf][0], afr[mf][1], afr[mf][2], afr[mf][3],
                       ph + (a_row + mf * 16) * PH_LD + ks * 16 + a_koff);
            uint32_t bfr[2][2];
            LDM_X4(bfr[0][0], bfr[0][1], bfr[1][0], bfr[1][1],
                   vt + b_row * VT_LD + ks * 16 + b_koff);
#pragma unroll
            for (int mf = 0; mf < 4; mf++)
#pragma unroll
                for (int nf = 0; nf < 2; nf++)
                    MMA_F16(o[mf][nf], afr[mf], bfr[nf][0], bfr[nf][1]);
        }

#pragma unroll
        for (int mf = 0; mf < 4; mf++) {
            int r0 = wm * 64 + mf * 16 + (lane >> 2);
#pragma unroll
            for (int nf = 0; nf < 2; nf++) {
                int col = wn * 16 + nf * 8 + ((lane & 3) << 1);
#pragma unroll
                for (int half_i = 0; half_i < 2; half_i++) {
                    int a = r0 + half_i * 8;
                    int b = a >> 4, h = a & 15;
                    float rv = half_i ? rinv1[mf] : rinv0[mf];
                    __half* dst = g_ws + ((size_t)b * T_LEN + t) * EMBED
                                  + h * HDIM + col;
                    *(__half2*)dst = __floats2half2_rn(
                        o[mf][nf][2 * half_i] * rv,
                        o[mf][nf][2 * half_i + 1] * rv);
                }
            }
        }
    }
}

// ---------------------------------------------------------------------------
extern "C" void kernel_launch(void* const* d_in, const int* in_sizes, int n_in,
                              void* d_out, int out_size)
{
    const float* query = (const float*)d_in[0];
    // d_in[1] = key, d_in[2] = value: unused by the reference math
    const float* w_qkv = (const float*)d_in[3];
    const float* b_qkv = (const float*)d_in[4];
    const float* w_out = (const float*)d_in[5];
    const float* b_out = (const float*)d_in[6];
    float* out = (float*)d_out;

    cudaFuncSetAttribute(attn_kernel,
                         cudaFuncAttributeMaxDynamicSharedMemorySize, ATTN_SMEM);
    cudaFuncSetAttribute(gemm_f16_big<__half>,
                         cudaFuncAttributeMaxDynamicSharedMemorySize, GEMM_SMEM);
    cudaFuncSetAttribute(gemm_f16_big<float>,
                         cudaFuncAttributeMaxDynamicSharedMemorySize, GEMM_SMEM);

    __half *qkv_ptr, *ws_ptr, *qh_ptr, *wqkv_ptr, *wout_ptr;
    cudaGetSymbolAddress((void**)&qkv_ptr, g_qkv);
    cudaGetSymbolAddress((void**)&ws_ptr, g_ws);
    cudaGetSymbolAddress((void**)&qh_ptr, g_qh);
    cudaGetSymbolAddress((void**)&wqkv_ptr, g_wqkv);
    cudaGetSymbolAddress((void**)&wout_ptr, g_wout);

    // Convert fp16 GEMM operands (round-to-nearest).
    {
        int n4q = (MROWS * EMBED) / 4;
        to_half_kernel<<<(n4q + 255) / 256, 256>>>(query, qh_ptr, n4q);
        int n4w = (NQKV * EMBED) / 4;
        to_half_kernel<<<(n4w + 255) / 256, 256>>>(w_qkv, wqkv_ptr, n4w);
        int n4o = (EMBED * EMBED) / 4;
        to_half_kernel<<<(n4o + 255) / 256, 256>>>(w_out, wout_ptr, n4o);
    }

    // QKV GEMM: [16384,1024] @ [3072,1024]^T -> g_qkv (fp16)
    gemm_f16_big<__half><<<dim3(NQKV / BN, MROWS / BM), 256, GEMM_SMEM>>>(
        qh_ptr, wqkv_ptr, b_qkv, qkv_ptr, NQKV, EMBED);
    // fused per-t tensor-core attention -> g_ws [B,T,E] (fp16)
    attn_kernel<<<T_LEN, 256, ATTN_SMEM>>>();
    // out GEMM: [16384,1024] @ [1024,1024]^T -> out (fp32)
    gemm_f16_big<float><<<dim3(EMBED / BN, MROWS / BM), 256, GEMM_SMEM>>>(
        ws_ptr, wout_ptr, b_out, out, EMBED, EMBED);
}

// round 17
// speedup vs baseline: 1.6522x; 1.6522x over previous
#include <cuda_runtime.h>
#include <cuda_fp16.h>
#include <cstdint>

#define T_LEN 2048
#define BATCH 8
#define EMBED 1024
#define NHEADS 16
#define HDIM 64
#define BH 128            // BATCH * NHEADS
#define MROWS 16384       // T_LEN * BATCH
#define NQKV 3072         // 3 * EMBED

// ---- GEMM geometry (R14-validated): 128x128 block, 8 warps (2x4), 64x32 ----
#define BK 64             // k halves per tile (128B rows)
#define TLD 72            // smem leading dim (halves)
#define STAGES 3
#define TILEH (128 * TLD)
#define GEMM_SMEM (STAGES * 2 * TILEH * 2)   // 110592 B; x2 CTAs = 221KB/SM

// attention smem layout (bytes) -- 94 KB -> 2 CTAs/SM
#define QH_LD 72
#define VT_LD 136
#define PH_LD 136
#define OFF_QH   0
#define OFF_KH   (OFF_QH + BH * QH_LD * 2)
#define OFF_VT   (OFF_KH + BH * QH_LD * 2)
#define OFF_PH   (OFF_VT + HDIM * VT_LD * 2)
#define OFF_IQ   (OFF_PH + BH * PH_LD * 2)
#define OFF_IK   (OFF_IQ + BH * 4)
#define OFF_RMAX (OFF_IK + BH * 4)
#define OFF_RSUM (OFF_RMAX + 4 * BH * 4)
#define ATTN_SMEM (OFF_RSUM + 4 * BH * 4)    // 94208

// Scratch (allowed: __device__ globals, no dynamic allocation)
__device__ __half g_qkv[(size_t)MROWS * NQKV];    // [T*B, 3E] fp16
__device__ __half g_ws[(size_t)MROWS * EMBED];    // [B, T, E] fp16
__device__ __half g_qh[(size_t)MROWS * EMBED];    // query fp16
__device__ __half g_wqkv[(size_t)NQKV * EMBED];   // w_qkv fp16
__device__ __half g_wout[(size_t)EMBED * EMBED];  // w_out fp16

#define LDM_X4(r0, r1, r2, r3, p) \
    asm volatile("ldmatrix.sync.aligned.m8n8.x4.b16 {%0,%1,%2,%3}, [%4];\n" \
                 : "=r"(r0), "=r"(r1), "=r"(r2), "=r"(r3) \
                 : "r"((uint32_t)__cvta_generic_to_shared(p)))

#define MMA_F16(c, af, b0, b1) \
    asm volatile("mma.sync.aligned.m16n8k16.row.col.f32.f16.f16.f32 " \
                 "{%0,%1,%2,%3}, {%4,%5,%6,%7}, {%8,%9}, {%0,%1,%2,%3};\n" \
                 : "+f"((c)[0]), "+f"((c)[1]), "+f"((c)[2]), "+f"((c)[3]) \
                 : "r"((af)[0]), "r"((af)[1]), "r"((af)[2]), "r"((af)[3]), \
                   "r"(b0), "r"(b1))

// ---------------------------------------------------------------------------
// Elementwise fp32 -> fp16 conversion, float4-vectorized.
// ---------------------------------------------------------------------------
__global__ __launch_bounds__(256) void to_half_kernel(
    const float* __restrict__ x, __half* __restrict__ y, int n4)
{
    int i = blockIdx.x * blockDim.x + threadIdx.x;
    if (i < n4) {
        float4 v = ((const float4*)x)[i];
        __half2* y2 = (__half2*)y;
        y2[2 * i]     = __floats2half2_rn(v.x, v.y);
        y2[2 * i + 1] = __floats2half2_rn(v.z, v.w);
    }
}

// ---------------------------------------------------------------------------
// fp16 tensor-core GEMM (fp32 accumulate): C[m][n] = sum_k A[m][k]*B[n][k]+bias[n]
// R14-validated geometry: 128x128 block tile, BK=64 halves, 256 threads,
// 8 warps (2 m x 4 n), warp tile 64x32, 3-stage cp.async,
// __launch_bounds__(256,2) -> 2 CTAs/SM (regs capped 128).
// OutT = __half (QKV intermediate) or float (final output) - epilogue only.
// ---------------------------------------------------------------------------
template <typename OutT>
__global__ __launch_bounds__(256, 2) void gemm_f16_kernel(
    const __half* __restrict__ A, const __half* __restrict__ B,
    const float* __restrict__ bias, OutT* __restrict__ C,
    int N, int K)
{
    extern __shared__ __half smh[];
    const int tid  = threadIdx.x;
    const int lane = tid & 31;
    const int warp = tid >> 5;
    const int wm   = warp >> 2;        // 0..1
    const int wn   = warp & 3;         // 0..3
    const int bm   = blockIdx.y << 7;
    const int bn   = blockIdx.x << 7;

    const int lrow   = tid >> 3;       // 0..31
    const int lchunk = tid & 7;        // 0..7
    const __half* gA = A + (size_t)(bm + lrow) * K + lchunk * 8;
    const __half* gB = B + (size_t)(bn + lrow) * K + lchunk * 8;

    const int a_row  = wm * 64 + (lane & 15);
    const int a_koff = (lane >> 4) * 8;
    const int b_row  = wn * 32 + ((lane >> 4) & 1) * 8 + (lane & 7);
    const int b_koff = ((lane >> 3) & 1) * 8;

    float c[4][4][4];
#pragma unroll
    for (int mf = 0; mf < 4; mf++)
#pragma unroll
        for (int nf = 0; nf < 4; nf++)
#pragma unroll
            for (int r = 0; r < 4; r++) c[mf][nf][r] = 0.0f;

    const int ntiles = K >> 6;

#define LOAD_TILE(s, k0) do {                                                  \
    __half* As_ = smh + (s) * (2 * TILEH);                                     \
    __half* Bs_ = As_ + TILEH;                                                 \
    _Pragma("unroll")                                                          \
    for (int i_ = 0; i_ < 4; i_++) {                                           \
        uint32_t sa_ = (uint32_t)__cvta_generic_to_shared(                     \
            As_ + (lrow + i_ * 32) * TLD + lchunk * 8);                        \
        asm volatile("cp.async.cg.shared.global [%0], [%1], 16;\n"             \
                     :: "r"(sa_), "l"(gA + (size_t)(i_ * 32) * K + (k0)));     \
        uint32_t sb_ = (uint32_t)__cvta_generic_to_shared(                     \
            Bs_ + (lrow + i_ * 32) * TLD + lchunk * 8);                        \
        asm volatile("cp.async.cg.shared.global [%0], [%1], 16;\n"             \
                     :: "r"(sb_), "l"(gB + (size_t)(i_ * 32) * K + (k0)));     \
    }                                                                          \
} while (0)

#pragma unroll
    for (int s = 0; s < STAGES - 1; s++) {
        LOAD_TILE(s, s * BK);
        asm volatile("cp.async.commit_group;\n");
    }

    for (int kt = 0; kt < ntiles; kt++) {
        asm volatile("cp.async.wait_group %0;\n" :: "n"(STAGES - 2));
        __syncthreads();

        int pf = kt + STAGES - 1;
        if (pf < ntiles) LOAD_TILE(pf % STAGES, pf * BK);
        asm volatile("cp.async.commit_group;\n");

        const __half* As = smh + (kt % STAGES) * (2 * TILEH);
        const __half* Bs = As + TILEH;

#pragma unroll
        for (int ks = 0; ks < 4; ks++) {
            uint32_t afr[4][4];
#pragma unroll
            for (int mf = 0; mf < 4; mf++)
                LDM_X4(afr[mf][0], afr[mf][1], afr[mf][2], afr[mf][3],
                       As + (a_row + mf * 16) * TLD + ks * 16 + a_koff);
            uint32_t bfr[4][2];
#pragma unroll
            for (int bi = 0; bi < 2; bi++)
                LDM_X4(bfr[2 * bi][0], bfr[2 * bi][1],
                       bfr[2 * bi + 1][0], bfr[2 * bi + 1][1],
                       Bs + (b_row + bi * 16) * TLD + ks * 16 + b_koff);
#pragma unroll
            for (int mf = 0; mf < 4; mf++)
#pragma unroll
                for (int nf = 0; nf < 4; nf++)
                    MMA_F16(c[mf][nf], afr[mf], bfr[nf][0], bfr[nf][1]);
        }
    }

    // epilogue
#pragma unroll
    for (int mf = 0; mf < 4; mf++) {
        int r0 = bm + wm * 64 + mf * 16 + (lane >> 2);
#pragma unroll
        for (int nf = 0; nf < 4; nf++) {
            int col = bn + wn * 32 + nf * 8 + ((lane & 3) << 1);
            float2 bv = *(const float2*)(bias + col);
            float v00 = c[mf][nf][0] + bv.x, v01 = c[mf][nf][1] + bv.y;
            float v10 = c[mf][nf][2] + bv.x, v11 = c[mf][nf][3] + bv.y;
            if (sizeof(OutT) == 2) {
                *(__half2*)((__half*)C + (size_t)r0 * N + col)
                    = __floats2half2_rn(v00, v01);
                *(__half2*)((__half*)C + (size_t)(r0 + 8) * N + col)
                    = __floats2half2_rn(v10, v11);
            } else {
                *(float2*)((float*)C + (size_t)r0 * N + col)
                    = make_float2(v00, v01);
                *(float2*)((float*)C + (size_t)(r0 + 8) * N + col)
                    = make_float2(v10, v11);
            }
        }
    }
#undef LOAD_TILE
}

// ---------------------------------------------------------------------------
// Per-t tensor-core attention, register-resident softmax. g_qkv is fp16:
// straight uint4 copies into tiles. (R14 logic, R16 fp16 loads - validated.)
// ---------------------------------------------------------------------------
__global__ __launch_bounds__(256, 2) void attn_kernel()
{
    extern __shared__ char smem[];
    __half* qh   = (__half*)(smem + OFF_QH);   // 128 x 72
    __half* kh   = (__half*)(smem + OFF_KH);   // 128 x 72
    __half* vt   = (__half*)(smem + OFF_VT);   // 64 x 136 (transposed: [d][j])
    __half* ph   = (__half*)(smem + OFF_PH);   // 128 x 136 (exp values)
    float*  invq = (float*)(smem + OFF_IQ);    // 128
    float*  invk = (float*)(smem + OFF_IK);    // 128
    float*  rmax = (float*)(smem + OFF_RMAX);  // [4][128]
    float*  rsum = (float*)(smem + OFF_RSUM);  // [4][128]

    const int t = blockIdx.x;
    const int tid = threadIdx.x;
    const int lane = tid & 31;
    const int warp = tid >> 5;
    const int wm = warp >> 2;      // 0..1
    const int wn = warp & 3;       // 0..3

    // Load q,k,v (fp16, 16B chunks); v stored transposed vt[d][j]
    for (int idx = tid; idx < BH * (HDIM / 8); idx += 256) {
        int a  = idx >> 3;                 // row 0..127
        int d8 = (idx & 7) << 3;           // 0,8,..,56
        int b = a >> 4, h = a & 15;
        const __half* base = g_qkv + (size_t)(t * BATCH + b) * NQKV
                             + h * HDIM + d8;
        uint4 qv = *(const uint4*)(base);
        uint4 kv = *(const uint4*)(base + EMBED);
        uint4 vv = *(const uint4*)(base + 2 * EMBED);
        *(uint4*)(qh + a * QH_LD + d8) = qv;
        *(uint4*)(kh + a * QH_LD + d8) = kv;
        const __half* vh = (const __half*)&vv;
#pragma unroll
        for (int j = 0; j < 8; j++)
            vt[(d8 + j) * VT_LD + a] = vh[j];
    }
    __syncthreads();

    // Row norms over fp16 values
    {
        const __half2* r = (const __half2*)((tid < BH ? qh : kh)
                            + (tid & 127) * QH_LD);
        float s = 0.0f;
#pragma unroll
        for (int d = 0; d < HDIM / 2; d++) {
            float2 f = __half22float2(r[d]);
            s = fmaf(f.x, f.x, fmaf(f.y, f.y, s));
        }
        float inv = rsqrtf(s);
        if (tid < BH) invq[tid] = inv; else invk[tid - BH] = inv;
    }
    __syncthreads();

    const int a_row  = wm * 64 + (lane & 15);
    const int a_koff = (lane >> 4) * 8;

    // S = qh @ kh^T (fp32 accum)
    float c[4][4][4];
    {
        const int b_row  = wn * 32 + ((lane >> 4) & 1) * 8 + (lane & 7);
        const int b_koff = ((lane >> 3) & 1) * 8;
#pragma unroll
        for (int mf = 0; mf < 4; mf++)
#pragma unroll
            for (int nf = 0; nf < 4; nf++)
#pragma unroll
                for (int r = 0; r < 4; r++) c[mf][nf][r] = 0.0f;

#pragma unroll
        for (int ks = 0; ks < 4; ks++) {
            uint32_t afr[4][4];
#pragma unroll
            for (int mf = 0; mf < 4; mf++)
                LDM_X4(afr[mf][0], afr[mf][1], afr[mf][2], afr[mf][3],
                       qh + (a_row + mf * 16) * QH_LD + ks * 16 + a_koff);
            uint32_t bfr[4][2];
#pragma unroll
            for (int bi = 0; bi < 2; bi++)
                LDM_X4(bfr[2 * bi][0], bfr[2 * bi][1],
                       bfr[2 * bi + 1][0], bfr[2 * bi + 1][1],
                       kh + (b_row + bi * 16) * QH_LD + ks * 16 + b_koff);
#pragma unroll
            for (int mf = 0; mf < 4; mf++)
#pragma unroll
                for (int nf = 0; nf < 4; nf++)
                    MMA_F16(c[mf][nf], afr[mf], bfr[nf][0], bfr[nf][1]);
        }
    }

    // Scale, per-warp row maxima via shfl, publish
#pragma unroll
    for (int mf = 0; mf < 4; mf++) {
        int r0 = wm * 64 + mf * 16 + (lane >> 2);
        float s0 = invq[r0] * 0.125f;
        float s1 = invq[r0 + 8] * 0.125f;
        float m0 = -1e30f, m1 = -1e30f;
#pragma unroll
        for (int nf = 0; nf < 4; nf++) {
            int col = wn * 32 + nf * 8 + ((lane & 3) << 1);
            float k0 = invk[col], k1 = invk[col + 1];
            c[mf][nf][0] *= s0 * k0; c[mf][nf][1] *= s0 * k1;
            c[mf][nf][2] *= s1 * k0; c[mf][nf][3] *= s1 * k1;
            m0 = fmaxf(m0, fmaxf(c[mf][nf][0], c[mf][nf][1]));
            m1 = fmaxf(m1, fmaxf(c[mf][nf][2], c[mf][nf][3]));
        }
        m0 = fmaxf(m0, __shfl_xor_sync(0xffffffffu, m0, 1));
        m0 = fmaxf(m0, __shfl_xor_sync(0xffffffffu, m0, 2));
        m1 = fmaxf(m1, __shfl_xor_sync(0xffffffffu, m1, 1));
        m1 = fmaxf(m1, __shfl_xor_sync(0xffffffffu, m1, 2));
        if ((lane & 3) == 0) {
            rmax[wn * BH + r0]     = m0;
            rmax[wn * BH + r0 + 8] = m1;
        }
    }
    __syncthreads();

    // exp(s - rowmax) -> ph (fp16, unnormalized), publish row sums
#pragma unroll
    for (int mf = 0; mf < 4; mf++) {
        int r0 = wm * 64 + mf * 16 + (lane >> 2);
        float M0 = fmaxf(fmaxf(rmax[r0], rmax[BH + r0]),
                         fmaxf(rmax[2 * BH + r0], rmax[3 * BH + r0]));
        float M1 = fmaxf(fmaxf(rmax[r0 + 8], rmax[BH + r0 + 8]),
                         fmaxf(rmax[2 * BH + r0 + 8], rmax[3 * BH + r0 + 8]));
        float sum0 = 0.0f, sum1 = 0.0f;
#pragma unroll
        for (int nf = 0; nf < 4; nf++) {
            int col = wn * 32 + nf * 8 + ((lane & 3) << 1);
            float e0 = __expf(c[mf][nf][0] - M0);
            float e1 = __expf(c[mf][nf][1] - M0);
            float e2 = __expf(c[mf][nf][2] - M1);
            float e3 = __expf(c[mf][nf][3] - M1);
            sum0 += e0 + e1; sum1 += e2 + e3;
            *(__half2*)(ph + r0 * PH_LD + col)       = __floats2half2_rn(e0, e1);
            *(__half2*)(ph + (r0 + 8) * PH_LD + col) = __floats2half2_rn(e2, e3);
        }
        sum0 += __shfl_xor_sync(0xffffffffu, sum0, 1);
        sum0 += __shfl_xor_sync(0xffffffffu, sum0, 2);
        sum1 += __shfl_xor_sync(0xffffffffu, sum1, 1);
        sum1 += __shfl_xor_sync(0xffffffffu, sum1, 2);
        if ((lane & 3) == 0) {
            rsum[wn * BH + r0]     = sum0;
            rsum[wn * BH + r0 + 8] = sum1;
        }
    }
    __syncthreads();

    float rinv0[4], rinv1[4];
#pragma unroll
    for (int mf = 0; mf < 4; mf++) {
        int r0 = wm * 64 + mf * 16 + (lane >> 2);
        rinv0[mf] = 1.0f / (rsum[r0] + rsum[BH + r0]
                            + rsum[2 * BH + r0] + rsum[3 * BH + r0]);
        rinv1[mf] = 1.0f / (rsum[r0 + 8] + rsum[BH + r0 + 8]
                            + rsum[2 * BH + r0 + 8] + rsum[3 * BH + r0 + 8]);
    }

    // ws = (1/sum) * E @ V
    {
        const int b_row  = wn * 16 + ((lane >> 4) & 1) * 8 + (lane & 7);
        const int b_koff = ((lane >> 3) & 1) * 8;

        float o[4][2][4];
#pragma unroll
        for (int mf = 0; mf < 4; mf++)
#pragma unroll
            for (int nf = 0; nf < 2; nf++)
#pragma unroll
                for (int r = 0; r < 4; r++) o[mf][nf][r] = 0.0f;

#pragma unroll
        for (int ks = 0; ks < 8; ks++) {
            uint32_t afr[4][4];
#pragma unroll
            for (int mf = 0; mf < 4; mf++)
                LDM_X4(afr[mf][0], afr[mf][1], afr[mf][2], afr[mf][3],
                       ph + (a_row + mf * 16) * PH_LD + ks * 16 + a_koff);
            uint32_t bfr[2][2];
            LDM_X4(bfr[0][0], bfr[0][1], bfr[1][0], bfr[1][1],
                   vt + b_row * VT_LD + ks * 16 + b_koff);
#pragma unroll
            for (int mf = 0; mf < 4; mf++)
#pragma unroll
                for (int nf = 0; nf < 2; nf++)
                    MMA_F16(o[mf][nf], afr[mf], bfr[nf][0], bfr[nf][1]);
        }

#pragma unroll
        for (int mf = 0; mf < 4; mf++) {
            int r0 = wm * 64 + mf * 16 + (lane >> 2);
#pragma unroll
            for (int nf = 0; nf < 2; nf++) {
                int col = wn * 16 + nf * 8 + ((lane & 3) << 1);
#pragma unroll
                for (int half_i = 0; half_i < 2; half_i++) {
                    int a = r0 + half_i * 8;
                    int b = a >> 4, h = a & 15;
                    float rv = half_i ? rinv1[mf] : rinv0[mf];
                    __half* dst = g_ws + ((size_t)b * T_LEN + t) * EMBED
                                  + h * HDIM + col;
                    *(__half2*)dst = __floats2half2_rn(
                        o[mf][nf][2 * half_i] * rv,
                        o[mf][nf][2 * half_i + 1] * rv);
                }
            }
        }
    }
}

// ---------------------------------------------------------------------------
extern "C" void kernel_launch(void* const* d_in, const int* in_sizes, int n_in,
                              void* d_out, int out_size)
{
    const float* query = (const float*)d_in[0];
    // d_in[1] = key, d_in[2] = value: unused by the reference math
    const float* w_qkv = (const float*)d_in[3];
    const float* b_qkv = (const float*)d_in[4];
    const float* w_out = (const float*)d_in[5];
    const float* b_out = (const float*)d_in[6];
    float* out = (float*)d_out;

    cudaFuncSetAttribute(attn_kernel,
                         cudaFuncAttributeMaxDynamicSharedMemorySize, ATTN_SMEM);
    cudaFuncSetAttribute(gemm_f16_kernel<__half>,
                         cudaFuncAttributeMaxDynamicSharedMemorySize, GEMM_SMEM);
    cudaFuncSetAttribute(gemm_f16_kernel<float>,
                         cudaFuncAttributeMaxDynamicSharedMemorySize, GEMM_SMEM);

    __half *qkv_ptr, *ws_ptr, *qh_ptr, *wqkv_ptr, *wout_ptr;
    cudaGetSymbolAddress((void**)&qkv_ptr, g_qkv);
    cudaGetSymbolAddress((void**)&ws_ptr, g_ws);
    cudaGetSymbolAddress((void**)&qh_ptr, g_qh);
    cudaGetSymbolAddress((void**)&wqkv_ptr, g_wqkv);
    cudaGetSymbolAddress((void**)&wout_ptr, g_wout);

    // Convert fp16 GEMM operands (round-to-nearest).
    {
        int n4q = (MROWS * EMBED) / 4;
        to_half_kernel<<<(n4q + 255) / 256, 256>>>(query, qh_ptr, n4q);
        int n4w = (NQKV * EMBED) / 4;
        to_half_kernel<<<(n4w + 255) / 256, 256>>>(w_qkv, wqkv_ptr, n4w);
        int n4o = (EMBED * EMBED) / 4;
        to_half_kernel<<<(n4o + 255) / 256, 256>>>(w_out, wout_ptr, n4o);
    }

    // QKV GEMM: [16384,1024] @ [3072,1024]^T -> g_qkv (fp16)
    gemm_f16_kernel<__half><<<dim3(NQKV / 128, MROWS / 128), 256, GEMM_SMEM>>>(
        qh_ptr, wqkv_ptr, b_qkv, qkv_ptr, NQKV, EMBED);
    // fused per-t tensor-core attention -> g_ws [B,T,E] (fp16)
    attn_kernel<<<T_LEN, 256, ATTN_SMEM>>>();
    // out GEMM: [16384,1024] @ [1024,1024]^T -> out (fp32)
    gemm_f16_kernel<float><<<dim3(EMBED / 128, MROWS / 128), 256, GEMM_SMEM>>>(
        ws_ptr, wout_ptr, b_out, out, EMBED, EMBED);
}